// round 4
// baseline (speedup 1.0000x reference)
#include <cuda_runtime.h>
#include <cstdint>

// y[b] = a0 + sum_k bk[k] * tanh( dot(ck[k,:], z[b,:]) + dk[k] )
// B = 2097152, Z = 16, K = 64.
//
// Strategy (SIMT baseline, compute-bound):
//  - each thread computes TWO batch elements (b, b+B/2) via packed fp32x2 FMA
//    (Blackwell fma.rn.f32x2 -> FFMA2, 2x fp32 FMA throughput)
//  - ck pre-duplicated in shared as {c,c} pairs so one LDS.128 feeds two FFMA2;
//    all lanes read the same address -> broadcast, no crossbar penalty
//  - tanh via MUFU (tanh.approx.f32), abs err ~5e-4 per h -> ~2e-4 on y (norm)
//  - two independent FFMA2 accumulator chains per k for ILP

constexpr int Z = 16;
constexpr int K = 64;
constexpr int THREADS = 256;

__device__ __forceinline__ unsigned long long pack2(float lo, float hi) {
    unsigned long long d;
    asm("mov.b64 %0, {%1, %2};"
        : "=l"(d) : "r"(__float_as_uint(lo)), "r"(__float_as_uint(hi)));
    return d;
}

__device__ __forceinline__ void unpack2(unsigned long long v, float& lo, float& hi) {
    unsigned int l, h;
    asm("mov.b64 {%0, %1}, %2;" : "=r"(l), "=r"(h) : "l"(v));
    lo = __uint_as_float(l);
    hi = __uint_as_float(h);
}

__device__ __forceinline__ unsigned long long fma2(unsigned long long a,
                                                   unsigned long long b,
                                                   unsigned long long c) {
    unsigned long long d;
    asm("fma.rn.f32x2 %0, %1, %2, %3;" : "=l"(d) : "l"(a), "l"(b), "l"(c));
    return d;
}

__device__ __forceinline__ unsigned long long add2(unsigned long long a,
                                                   unsigned long long b) {
    unsigned long long d;
    asm("add.rn.f32x2 %0, %1, %2;" : "=l"(d) : "l"(a), "l"(b));
    return d;
}

__device__ __forceinline__ float tanh_fast(float x) {
    float t;
    asm("tanh.approx.f32 %0, %1;" : "=f"(t) : "f"(x));
    return t;
}

__global__ __launch_bounds__(THREADS)
void mave_ge_kernel(const float* __restrict__ z,
                    const float* __restrict__ a0,
                    const float* __restrict__ bk,
                    const float* __restrict__ ck,
                    const float* __restrict__ dk,
                    float* __restrict__ y,
                    int half) {
    // ck duplicated: ckd[k][2j] = ckd[k][2j+1] = ck[k][j]; row = 128B, 16B aligned
    __shared__ __align__(16) float ckd[K][2 * Z];
    __shared__ float bks[K];
    __shared__ unsigned long long dk2[K];
    __shared__ float a0s;

    const int tid = threadIdx.x;

    for (int i = tid; i < K * Z; i += THREADS) {
        float c = ck[i];
        int k = i >> 4;
        int j = i & 15;
        ckd[k][2 * j + 0] = c;
        ckd[k][2 * j + 1] = c;
    }
    for (int i = tid; i < K; i += THREADS) {
        bks[i] = bk[i];
        float d = dk[i];
        dk2[i] = pack2(d, d);
    }
    if (tid == 0) a0s = a0[0];
    __syncthreads();

    const long t = (long)blockIdx.x * THREADS + tid;

    // two coalesced batch streams: b0 = t, b1 = t + half
    const float4* zp0 = reinterpret_cast<const float4*>(z) + t * (Z / 4);
    const float4* zp1 = reinterpret_cast<const float4*>(z) + (t + (long)half) * (Z / 4);

    float4 za[4], zb[4];
#pragma unroll
    for (int i = 0; i < 4; i++) {
        za[i] = zp0[i];
        zb[i] = zp1[i];
    }

    unsigned long long z2[Z];
#pragma unroll
    for (int i = 0; i < 4; i++) {
        z2[4 * i + 0] = pack2(za[i].x, zb[i].x);
        z2[4 * i + 1] = pack2(za[i].y, zb[i].y);
        z2[4 * i + 2] = pack2(za[i].z, zb[i].z);
        z2[4 * i + 3] = pack2(za[i].w, zb[i].w);
    }

    float y0 = a0s;
    float y1 = a0s;

#pragma unroll 4
    for (int k = 0; k < K; k++) {
        const ulonglong2* row = reinterpret_cast<const ulonglong2*>(&ckd[k][0]);
        unsigned long long acc0 = dk2[k];       // {dk, dk}
        unsigned long long acc1 = 0ULL;         // {0, 0}
#pragma unroll
        for (int jj = 0; jj < 8; jj++) {
            ulonglong2 cc = row[jj];            // LDS.128 broadcast: {c_{2jj} dup, c_{2jj+1} dup}
            acc0 = fma2(z2[2 * jj + 0], cc.x, acc0);
            acc1 = fma2(z2[2 * jj + 1], cc.y, acc1);
        }
        unsigned long long hs = add2(acc0, acc1);
        float h0, h1;
        unpack2(hs, h0, h1);
        float bkk = bks[k];
        y0 = fmaf(bkk, tanh_fast(h0), y0);
        y1 = fmaf(bkk, tanh_fast(h1), y1);
    }

    y[t] = y0;
    y[t + half] = y1;
}

extern "C" void kernel_launch(void* const* d_in, const int* in_sizes, int n_in,
                              void* d_out, int out_size) {
    const float* z  = (const float*)d_in[0];
    const float* a0 = (const float*)d_in[1];
    const float* bk = (const float*)d_in[2];
    const float* ck = (const float*)d_in[3];
    const float* dk = (const float*)d_in[4];
    float* y = (float*)d_out;

    const int B = in_sizes[0] / Z;   // 2097152
    const int half = B / 2;          // 1048576
    const int blocks = half / THREADS;  // 4096

    mave_ge_kernel<<<blocks, THREADS>>>(z, a0, bk, ck, dk, y, half);
}

// round 8
// speedup vs baseline: 1.2535x; 1.2535x over previous
#include <cuda_runtime.h>
#include <cstdint>

// y[b] = a0 + sum_k bk[k] * tanh( dot(ck[k,:], z[b,:]) + dk[k] )
// B = 2097152, Z = 16, K = 64.
//
// R4 finding: broadcast LDS pays full crossbar return bandwidth (measured
// ~227B/cyc/SM at 94.5% L1 => peak ~256B/cyc) -> 2-stream kernel was
// L1-bound at 4:1 LDS:FMA. Fix: 4 batch elements per thread (two f32x2
// pair-streams), so each 8-LDS.128 ck row feeds 32 FFMA2 -> LDS and FMA
// co-bound at the ~63us FFMA2 pipe floor. Predicted 65-80us.

constexpr int Z = 16;
constexpr int K = 64;
constexpr int THREADS = 256;

__device__ __forceinline__ unsigned long long pack2(float lo, float hi) {
    unsigned long long d;
    asm("mov.b64 %0, {%1, %2};"
        : "=l"(d) : "r"(__float_as_uint(lo)), "r"(__float_as_uint(hi)));
    return d;
}

__device__ __forceinline__ void unpack2(unsigned long long v, float& lo, float& hi) {
    unsigned int l, h;
    asm("mov.b64 {%0, %1}, %2;" : "=r"(l), "=r"(h) : "l"(v));
    lo = __uint_as_float(l);
    hi = __uint_as_float(h);
}

__device__ __forceinline__ unsigned long long fma2(unsigned long long a,
                                                   unsigned long long b,
                                                   unsigned long long c) {
    unsigned long long d;
    asm("fma.rn.f32x2 %0, %1, %2, %3;" : "=l"(d) : "l"(a), "l"(b), "l"(c));
    return d;
}

__device__ __forceinline__ unsigned long long add2(unsigned long long a,
                                                   unsigned long long b) {
    unsigned long long d;
    asm("add.rn.f32x2 %0, %1, %2;" : "=l"(d) : "l"(a), "l"(b));
    return d;
}

__device__ __forceinline__ float tanh_fast(float x) {
    float t;
    asm("tanh.approx.f32 %0, %1;" : "=f"(t) : "f"(x));
    return t;
}

__global__ __launch_bounds__(THREADS, 2)
void mave_ge_kernel(const float* __restrict__ z,
                    const float* __restrict__ a0,
                    const float* __restrict__ bk,
                    const float* __restrict__ ck,
                    const float* __restrict__ dk,
                    float* __restrict__ y,
                    int quarter) {
    // ck duplicated: ckd[k][2j] = ckd[k][2j+1] = ck[k][j]; row = 128B, 16B aligned
    __shared__ __align__(16) float ckd[K][2 * Z];
    __shared__ float bks[K];
    __shared__ unsigned long long dk2[K];
    __shared__ float a0s;

    const int tid = threadIdx.x;

    for (int i = tid; i < K * Z; i += THREADS) {
        float c = ck[i];
        int k = i >> 4;
        int j = i & 15;
        ckd[k][2 * j + 0] = c;
        ckd[k][2 * j + 1] = c;
    }
    for (int i = tid; i < K; i += THREADS) {
        bks[i] = bk[i];
        float d = dk[i];
        dk2[i] = pack2(d, d);
    }
    if (tid == 0) a0s = a0[0];
    __syncthreads();

    const long t = (long)blockIdx.x * THREADS + tid;
    const long q = (long)quarter;

    // four coalesced batch streams: b0=t, b1=t+q, b2=t+2q, b3=t+3q
    const float4* zp0 = reinterpret_cast<const float4*>(z) + (t        ) * (Z / 4);
    const float4* zp1 = reinterpret_cast<const float4*>(z) + (t +     q) * (Z / 4);
    const float4* zp2 = reinterpret_cast<const float4*>(z) + (t + 2 * q) * (Z / 4);
    const float4* zp3 = reinterpret_cast<const float4*>(z) + (t + 3 * q) * (Z / 4);

    float4 za[4], zb[4], zc[4], zd[4];
#pragma unroll
    for (int i = 0; i < 4; i++) {
        za[i] = zp0[i];
        zb[i] = zp1[i];
        zc[i] = zp2[i];
        zd[i] = zp3[i];
    }

    // p01[j] = {z_b0[j], z_b1[j]}, p23[j] = {z_b2[j], z_b3[j]}
    unsigned long long p01[Z], p23[Z];
#pragma unroll
    for (int i = 0; i < 4; i++) {
        p01[4 * i + 0] = pack2(za[i].x, zb[i].x);
        p01[4 * i + 1] = pack2(za[i].y, zb[i].y);
        p01[4 * i + 2] = pack2(za[i].z, zb[i].z);
        p01[4 * i + 3] = pack2(za[i].w, zb[i].w);
        p23[4 * i + 0] = pack2(zc[i].x, zd[i].x);
        p23[4 * i + 1] = pack2(zc[i].y, zd[i].y);
        p23[4 * i + 2] = pack2(zc[i].z, zd[i].z);
        p23[4 * i + 3] = pack2(zc[i].w, zd[i].w);
    }

    float y0 = a0s, y1 = a0s, y2 = a0s, y3 = a0s;

#pragma unroll 2
    for (int k = 0; k < K; k++) {
        const ulonglong2* row = reinterpret_cast<const ulonglong2*>(&ckd[k][0]);
        unsigned long long dkk = dk2[k];
        unsigned long long a01_0 = dkk, a01_1 = 0ULL;
        unsigned long long a23_0 = dkk, a23_1 = 0ULL;
#pragma unroll
        for (int jj = 0; jj < 8; jj++) {
            ulonglong2 cc = row[jj];  // LDS.128 bcast: {c_{2jj} dup, c_{2jj+1} dup}
            a01_0 = fma2(p01[2 * jj + 0], cc.x, a01_0);
            a23_0 = fma2(p23[2 * jj + 0], cc.x, a23_0);
            a01_1 = fma2(p01[2 * jj + 1], cc.y, a01_1);
            a23_1 = fma2(p23[2 * jj + 1], cc.y, a23_1);
        }
        unsigned long long h01 = add2(a01_0, a01_1);
        unsigned long long h23 = add2(a23_0, a23_1);
        float h0, h1, h2, h3;
        unpack2(h01, h0, h1);
        unpack2(h23, h2, h3);
        float bkk = bks[k];
        y0 = fmaf(bkk, tanh_fast(h0), y0);
        y1 = fmaf(bkk, tanh_fast(h1), y1);
        y2 = fmaf(bkk, tanh_fast(h2), y2);
        y3 = fmaf(bkk, tanh_fast(h3), y3);
    }

    y[t]         = y0;
    y[t + q]     = y1;
    y[t + 2 * q] = y2;
    y[t + 3 * q] = y3;
}

extern "C" void kernel_launch(void* const* d_in, const int* in_sizes, int n_in,
                              void* d_out, int out_size) {
    const float* z  = (const float*)d_in[0];
    const float* a0 = (const float*)d_in[1];
    const float* bk = (const float*)d_in[2];
    const float* ck = (const float*)d_in[3];
    const float* dk = (const float*)d_in[4];
    float* y = (float*)d_out;

    const int B = in_sizes[0] / Z;      // 2097152
    const int quarter = B / 4;          // 524288
    const int blocks = quarter / THREADS;  // 2048

    mave_ge_kernel<<<blocks, THREADS>>>(z, a0, bk, ck, dk, y, quarter);
}

// round 10
// speedup vs baseline: 1.2766x; 1.0184x over previous
#include <cuda_runtime.h>
#include <cstdint>

// y[b] = a0 + sum_k bk[k] * tanh( dot(ck[k,:], z[b,:]) + dk[k] )
// B = 2097152, Z = 16, K = 64.
//
// R8 finding: 4-elem batch-pair kernel halved LDS (L1 94.5->66.3%) but went
// latency-bound (occ 23%, fma 53.6%, regs 120). This round: j-pair f32x2
// packing -- lanes are {even j, odd j} of the SAME output, so ck needs NO
// smem duplication (4 LDS.128/k, natural layout) and z needs NO register
// duplication (float4 loads are already j-pairs). LDS traffic halves again
// (4.3GB -> 2.15GB) at identical FMA work and same register footprint.
// Predicted ~78-90us, fma -> ~75%.

constexpr int Z = 16;
constexpr int K = 64;
constexpr int THREADS = 256;

__device__ __forceinline__ unsigned long long pack2(float lo, float hi) {
    unsigned long long d;
    asm("mov.b64 %0, {%1, %2};"
        : "=l"(d) : "r"(__float_as_uint(lo)), "r"(__float_as_uint(hi)));
    return d;
}

__device__ __forceinline__ void unpack2(unsigned long long v, float& lo, float& hi) {
    unsigned int l, h;
    asm("mov.b64 {%0, %1}, %2;" : "=r"(l), "=r"(h) : "l"(v));
    lo = __uint_as_float(l);
    hi = __uint_as_float(h);
}

__device__ __forceinline__ unsigned long long fma2(unsigned long long a,
                                                   unsigned long long b,
                                                   unsigned long long c) {
    unsigned long long d;
    asm("fma.rn.f32x2 %0, %1, %2, %3;" : "=l"(d) : "l"(a), "l"(b), "l"(c));
    return d;
}

__device__ __forceinline__ unsigned long long add2(unsigned long long a,
                                                   unsigned long long b) {
    unsigned long long d;
    asm("add.rn.f32x2 %0, %1, %2;" : "=l"(d) : "l"(a), "l"(b));
    return d;
}

__device__ __forceinline__ float tanh_fast(float x) {
    float t;
    asm("tanh.approx.f32 %0, %1;" : "=f"(t) : "f"(x));
    return t;
}

__global__ __launch_bounds__(THREADS, 2)
void mave_ge_kernel(const float* __restrict__ z,
                    const float* __restrict__ a0,
                    const float* __restrict__ bk,
                    const float* __restrict__ ck,
                    const float* __restrict__ dk,
                    float* __restrict__ y,
                    int quarter) {
    // ck in natural layout: cks[k][j], 64B per row, no duplication.
    __shared__ __align__(16) float cks[K][Z];
    __shared__ float bks[K];
    __shared__ unsigned long long dk20[K];   // {dk, 0}
    __shared__ float a0s;

    const int tid = threadIdx.x;

    for (int i = tid; i < K * Z; i += THREADS) {
        cks[i >> 4][i & 15] = ck[i];
    }
    for (int i = tid; i < K; i += THREADS) {
        bks[i] = bk[i];
        dk20[i] = pack2(dk[i], 0.0f);
    }
    if (tid == 0) a0s = a0[0];
    __syncthreads();

    const long t = (long)blockIdx.x * THREADS + tid;
    const long q = (long)quarter;

    // four coalesced batch streams: b_e = t + e*q
    const float4* zp0 = reinterpret_cast<const float4*>(z) + (t        ) * (Z / 4);
    const float4* zp1 = reinterpret_cast<const float4*>(z) + (t +     q) * (Z / 4);
    const float4* zp2 = reinterpret_cast<const float4*>(z) + (t + 2 * q) * (Z / 4);
    const float4* zp3 = reinterpret_cast<const float4*>(z) + (t + 3 * q) * (Z / 4);

    // pz[e][p] = {z[2p], z[2p+1]} for element e: natural j-pairs, no dup.
    unsigned long long pz[4][8];
#pragma unroll
    for (int i = 0; i < 4; i++) {
        float4 v0 = zp0[i];
        float4 v1 = zp1[i];
        float4 v2 = zp2[i];
        float4 v3 = zp3[i];
        pz[0][2 * i + 0] = pack2(v0.x, v0.y);
        pz[0][2 * i + 1] = pack2(v0.z, v0.w);
        pz[1][2 * i + 0] = pack2(v1.x, v1.y);
        pz[1][2 * i + 1] = pack2(v1.z, v1.w);
        pz[2][2 * i + 0] = pack2(v2.x, v2.y);
        pz[2][2 * i + 1] = pack2(v2.z, v2.w);
        pz[3][2 * i + 0] = pack2(v3.x, v3.y);
        pz[3][2 * i + 1] = pack2(v3.z, v3.w);
    }

    float y0 = a0s, y1 = a0s, y2 = a0s, y3 = a0s;

#pragma unroll 2
    for (int k = 0; k < K; k++) {
        // 4x LDS.128 broadcast: 8 j-pair packs of ck row k
        const ulonglong2* row = reinterpret_cast<const ulonglong2*>(&cks[k][0]);
        ulonglong2 c0 = row[0];   // {c0c1, c2c3}
        ulonglong2 c1 = row[1];   // {c4c5, c6c7}
        ulonglong2 c2 = row[2];   // {c8c9, c10c11}
        ulonglong2 c3 = row[3];   // {c12c13, c14c15}
        unsigned long long dkk = dk20[k];
        float bkk = bks[k];

        float h[4];
#pragma unroll
        for (int e = 0; e < 4; e++) {
            // two independent chains per element, 4 FFMA2 deep each
            unsigned long long accA = dkk;   // {dk, 0}
            unsigned long long accB = 0ULL;
            accA = fma2(pz[e][0], c0.x, accA);
            accB = fma2(pz[e][1], c0.y, accB);
            accA = fma2(pz[e][2], c1.x, accA);
            accB = fma2(pz[e][3], c1.y, accB);
            accA = fma2(pz[e][4], c2.x, accA);
            accB = fma2(pz[e][5], c2.y, accB);
            accA = fma2(pz[e][6], c3.x, accA);
            accB = fma2(pz[e][7], c3.y, accB);
            unsigned long long s = add2(accA, accB);
            float lo, hi;
            unpack2(s, lo, hi);
            h[e] = lo + hi;
        }
        y0 = fmaf(bkk, tanh_fast(h[0]), y0);
        y1 = fmaf(bkk, tanh_fast(h[1]), y1);
        y2 = fmaf(bkk, tanh_fast(h[2]), y2);
        y3 = fmaf(bkk, tanh_fast(h[3]), y3);
    }

    y[t]         = y0;
    y[t + q]     = y1;
    y[t + 2 * q] = y2;
    y[t + 3 * q] = y3;
}

extern "C" void kernel_launch(void* const* d_in, const int* in_sizes, int n_in,
                              void* d_out, int out_size) {
    const float* z  = (const float*)d_in[0];
    const float* a0 = (const float*)d_in[1];
    const float* bk = (const float*)d_in[2];
    const float* ck = (const float*)d_in[3];
    const float* dk = (const float*)d_in[4];
    float* y = (float*)d_out;

    const int B = in_sizes[0] / Z;      // 2097152
    const int quarter = B / 4;          // 524288
    const int blocks = quarter / THREADS;  // 2048

    mave_ge_kernel<<<blocks, THREADS>>>(z, a0, bk, ck, dk, y, quarter);
}

// round 11
// speedup vs baseline: 1.2788x; 1.0017x over previous
#include <cuda_runtime.h>
#include <cstdint>

// y[b] = a0 + sum_k bk[k] * tanh( dot(ck[k,:], z[b,:]) + dk[k] )
// B = 2097152, Z = 16, K = 64.
//
// R10 finding: j-pair packing halved LDS (L1 43.8%) but dur ~unchanged ->
// kernel is issue/latency-bound (occ 23.7%, issue 48.6%, fma 61.4%,
// regs 116 => only 4 warps/SMSP). This round: 3 batch elements/thread with
// __launch_bounds__(256,3) (85-reg budget) -> 24 warps/SM, 6/SMSP.
// LDS/output rises 4/3x (~50us busy, under fma floor ~78us). Predicted
// dur 84-92us, issue ->~70%, fma ->~75%.

constexpr int Z = 16;
constexpr int K = 64;
constexpr int THREADS = 256;

__device__ __forceinline__ unsigned long long pack2(float lo, float hi) {
    unsigned long long d;
    asm("mov.b64 %0, {%1, %2};"
        : "=l"(d) : "r"(__float_as_uint(lo)), "r"(__float_as_uint(hi)));
    return d;
}

__device__ __forceinline__ void unpack2(unsigned long long v, float& lo, float& hi) {
    unsigned int l, h;
    asm("mov.b64 {%0, %1}, %2;" : "=r"(l), "=r"(h) : "l"(v));
    lo = __uint_as_float(l);
    hi = __uint_as_float(h);
}

__device__ __forceinline__ unsigned long long fma2(unsigned long long a,
                                                   unsigned long long b,
                                                   unsigned long long c) {
    unsigned long long d;
    asm("fma.rn.f32x2 %0, %1, %2, %3;" : "=l"(d) : "l"(a), "l"(b), "l"(c));
    return d;
}

__device__ __forceinline__ unsigned long long add2(unsigned long long a,
                                                   unsigned long long b) {
    unsigned long long d;
    asm("add.rn.f32x2 %0, %1, %2;" : "=l"(d) : "l"(a), "l"(b));
    return d;
}

__device__ __forceinline__ float tanh_fast(float x) {
    float t;
    asm("tanh.approx.f32 %0, %1;" : "=f"(t) : "f"(x));
    return t;
}

__global__ __launch_bounds__(THREADS, 3)
void mave_ge_kernel(const float* __restrict__ z,
                    const float* __restrict__ a0,
                    const float* __restrict__ bk,
                    const float* __restrict__ ck,
                    const float* __restrict__ dk,
                    float* __restrict__ y,
                    int q, int Btot) {
    // ck in natural layout: cks[k][j], 64B per row, no duplication.
    __shared__ __align__(16) float cks[K][Z];
    __shared__ float bks[K];
    __shared__ unsigned long long dk20[K];   // {dk, 0}
    __shared__ float a0s;

    const int tid = threadIdx.x;

    for (int i = tid; i < K * Z; i += THREADS) {
        cks[i >> 4][i & 15] = ck[i];
    }
    for (int i = tid; i < K; i += THREADS) {
        bks[i] = bk[i];
        dk20[i] = pack2(dk[i], 0.0f);
    }
    if (tid == 0) a0s = a0[0];
    __syncthreads();

    const long t = (long)blockIdx.x * THREADS + tid;
    const long qq = (long)q;

    // three coalesced batch streams: t, t+q, t+2q (last predicated: B % 3 != 0)
    const long t2 = t + 2 * qq;
    const bool has3 = t2 < (long)Btot;
    const long t2c = has3 ? t2 : t;   // clamp to keep load in-bounds

    const float4* zp0 = reinterpret_cast<const float4*>(z) + (t     ) * (Z / 4);
    const float4* zp1 = reinterpret_cast<const float4*>(z) + (t + qq) * (Z / 4);
    const float4* zp2 = reinterpret_cast<const float4*>(z) + (t2c   ) * (Z / 4);

    // pz[e][p] = {z[2p], z[2p+1]} for element e: natural j-pairs, no dup.
    unsigned long long pz[3][8];
#pragma unroll
    for (int i = 0; i < 4; i++) {
        float4 v0 = zp0[i];
        float4 v1 = zp1[i];
        float4 v2 = zp2[i];
        pz[0][2 * i + 0] = pack2(v0.x, v0.y);
        pz[0][2 * i + 1] = pack2(v0.z, v0.w);
        pz[1][2 * i + 0] = pack2(v1.x, v1.y);
        pz[1][2 * i + 1] = pack2(v1.z, v1.w);
        pz[2][2 * i + 0] = pack2(v2.x, v2.y);
        pz[2][2 * i + 1] = pack2(v2.z, v2.w);
    }

    float y0 = a0s, y1 = a0s, y2 = a0s;

    for (int k = 0; k < K; k++) {
        // 4x LDS.128 broadcast: 8 j-pair packs of ck row k
        const ulonglong2* row = reinterpret_cast<const ulonglong2*>(&cks[k][0]);
        ulonglong2 c0 = row[0];   // {c0c1, c2c3}
        ulonglong2 c1 = row[1];   // {c4c5, c6c7}
        ulonglong2 c2 = row[2];   // {c8c9, c10c11}
        ulonglong2 c3 = row[3];   // {c12c13, c14c15}
        unsigned long long dkk = dk20[k];
        float bkk = bks[k];

        float h[3];
#pragma unroll
        for (int e = 0; e < 3; e++) {
            // two independent chains per element, 4 FFMA2 deep each
            unsigned long long accA = dkk;   // {dk, 0}
            unsigned long long accB = 0ULL;
            accA = fma2(pz[e][0], c0.x, accA);
            accB = fma2(pz[e][1], c0.y, accB);
            accA = fma2(pz[e][2], c1.x, accA);
            accB = fma2(pz[e][3], c1.y, accB);
            accA = fma2(pz[e][4], c2.x, accA);
            accB = fma2(pz[e][5], c2.y, accB);
            accA = fma2(pz[e][6], c3.x, accA);
            accB = fma2(pz[e][7], c3.y, accB);
            unsigned long long s = add2(accA, accB);
            float lo, hi;
            unpack2(s, lo, hi);
            h[e] = lo + hi;
        }
        y0 = fmaf(bkk, tanh_fast(h[0]), y0);
        y1 = fmaf(bkk, tanh_fast(h[1]), y1);
        y2 = fmaf(bkk, tanh_fast(h[2]), y2);
    }

    y[t]      = y0;
    y[t + qq] = y1;
    if (has3) y[t2] = y2;
}

extern "C" void kernel_launch(void* const* d_in, const int* in_sizes, int n_in,
                              void* d_out, int out_size) {
    const float* z  = (const float*)d_in[0];
    const float* a0 = (const float*)d_in[1];
    const float* bk = (const float*)d_in[2];
    const float* ck = (const float*)d_in[3];
    const float* dk = (const float*)d_in[4];
    float* y = (float*)d_out;

    const int B = in_sizes[0] / Z;                       // 2097152
    const int per = (B + 2) / 3;                         // ceil(B/3) = 699051
    const int blocks = (per + THREADS - 1) / THREADS;    // 2731
    const int q = blocks * THREADS;                      // 699136

    mave_ge_kernel<<<blocks, THREADS>>>(z, a0, bk, ck, dk, y, q, B);
}